// round 8
// baseline (speedup 1.0000x reference)
#include <cuda_runtime.h>

#define HID 64
#define NBATCH 256
#define SEQ 4096
#define NG 256   // 4*HID gates

// Scratch (no cudaMalloc allowed):
__device__ float g_seqA[(size_t)NBATCH * SEQ * HID];   // 256 MB
__device__ float g_seqB[(size_t)NBATCH * SEQ * HID];   // 256 MB
__device__ float g_xz[(size_t)NBATCH * SEQ * NG];      // 1 GB, gate-remapped

typedef unsigned long long ull;

static __device__ __forceinline__ ull pk2(float lo, float hi) {
    ull r;
    asm("mov.b64 %0, {%1,%2};" : "=l"(r) : "f"(lo), "f"(hi));
    return r;
}
static __device__ __forceinline__ void upk2(ull v, float& lo, float& hi) {
    asm("mov.b64 {%0,%1}, %2;" : "=f"(lo), "=f"(hi) : "l"(v));
}
static __device__ __forceinline__ void ffma2(ull& d, ull a, ull b) {
    asm("fma.rn.f32x2 %0, %1, %2, %0;" : "+l"(d) : "l"(a), "l"(b));
}
static __device__ __forceinline__ float ex2f(float x) {
    float r; asm("ex2.approx.f32 %0, %1;" : "=f"(r) : "f"(x)); return r;
}
static __device__ __forceinline__ float rcpf(float x) {
    float r; asm("rcp.approx.f32 %0, %1;" : "=f"(r) : "f"(x)); return r;
}
#define L2E 1.44269504088896f
// tanh(x) = 1 - 2/(2^(2*L2E*x)+1); overflow-safe both directions.
static __device__ __forceinline__ float tanh_f(float x) {
    return fmaf(-2.0f, rcpf(ex2f(x * (2.0f * L2E)) + 1.0f), 1.0f);
}

// gate remap: storage index tid <-> gate row jg = (tid&3)*HID + (tid>>2)

// ---------------------------------------------------------------------------
// xz precompute, DIN = 64 (gate-remapped output), layers 1-2 only.
// ---------------------------------------------------------------------------
__global__ void __launch_bounds__(256)
xz_din64_kernel(const float* __restrict__ in_seq,   // [B,SEQ,64]
                const float* __restrict__ Wih,      // [256,64]
                const float* __restrict__ bih,
                const float* __restrict__ bhh,
                float* __restrict__ xz) {
    __shared__ __align__(16) float sin_[32][HID];   // 8 KB
    const int tid = threadIdx.x;
    const int jg  = (tid & 3) * HID + (tid >> 2);
    const int b   = blockIdx.y;
    const int t0  = blockIdx.x * 32;

    const float* src = in_seq + ((size_t)b * SEQ + t0) * HID;
#pragma unroll
    for (int k = 0; k < 8; ++k)
        ((float*)sin_)[tid + k * 256] = src[tid + k * 256];

    ull wi[32];
#pragma unroll
    for (int p = 0; p < 32; ++p)
        wi[p] = pk2(Wih[jg * HID + 2 * p], Wih[jg * HID + 2 * p + 1]);
    const float bias = bih[jg] + bhh[jg];
    __syncthreads();

    float* o = xz + ((size_t)b * SEQ + t0) * NG + tid;
#pragma unroll 4
    for (int tt = 0; tt < 32; ++tt) {
        const ulonglong2* v = (const ulonglong2*)&sin_[tt][0];
        ull a0 = pk2(bias, 0.0f), a1 = 0ULL;
#pragma unroll
        for (int p = 0; p < 16; ++p) {
            ulonglong2 q = v[p];
            ffma2(a0, wi[2 * p], q.x);
            ffma2(a1, wi[2 * p + 1], q.y);
        }
        float l0, l1, h0, h1;
        upk2(a0, l0, h0); upk2(a1, l1, h1);
        o[(size_t)tt * NG] = (l0 + h0) + (l1 + h1);
    }
}

// ---------------------------------------------------------------------------
// Recurrent kernel v5.  TWO batches per CTA (in-thread ILP), 128 CTAs x 256
// threads, 1 CTA/SM.  Whh chunk registers shared across both batches.
// Thread (u = tid>>2, q = tid&3): partial dots of all 4 gates of unit u over
// h-chunk q, for batch A and batch B (independent chains, interleaved).
// Quad reduce-scatter (3 shuffles) -> lane q owns gate q; unified activation
// (1 ex2 + 1 rcp); quad gather (4 shuffles); 1 barrier/step.
// DIN1 mode (layer 0): xz computed inline from broadcast x scalar.
// ---------------------------------------------------------------------------
template <bool DIN1>
__global__ void __launch_bounds__(256)
lstm_rec_kernel(const float* __restrict__ x,        // DIN1: [B,SEQ]
                const float* __restrict__ xz,       // !DIN1: [B,SEQ,256] remapped
                const float* __restrict__ Wih,      // DIN1: [256,1]
                const float* __restrict__ bih,
                const float* __restrict__ bhh,
                const float* __restrict__ Whh,      // [256,64]
                float* __restrict__ out_seq,        // [B,SEQ,64]
                float* __restrict__ d_out,
                int layer) {
    __shared__ __align__(16) float sh[2][2][80];    // [parity][batch][chunked h]

    const int tid = threadIdx.x;
    const int b0  = blockIdx.x * 2;
    const int u   = tid >> 2;
    const int q   = tid & 3;
    const int jg  = q * HID + u;

    // Whh chunk: 4 gate rows of unit u, columns [16q, 16q+16) — shared A/B
    ull w[32];
#pragma unroll
    for (int g = 0; g < 4; ++g) {
        const int row = g * HID + u;
#pragma unroll
        for (int m = 0; m < 8; ++m)
            w[g * 8 + m] = pk2(Whh[row * HID + 16 * q + 2 * m],
                               Whh[row * HID + 16 * q + 2 * m + 1]);
    }

    // input-contribution state
    float wx = 0.0f, bias = 0.0f;
    const float* zA = nullptr;
    const float* zB = nullptr;
    const float* xA = nullptr;
    const float* xB = nullptr;
    float ringA[4], ringB[4];
    if (DIN1) {
        wx   = Wih[jg];
        bias = bih[jg] + bhh[jg];
        xA = x + (size_t)b0 * SEQ;
        xB = x + (size_t)(b0 + 1) * SEQ;
#pragma unroll
        for (int d = 0; d < 4; ++d) {
            ringA[d] = xA[d];
            ringB[d] = xB[d];
        }
    } else {
        zA = xz + (size_t)b0 * SEQ * NG + tid;
        zB = xz + (size_t)(b0 + 1) * SEQ * NG + tid;
#pragma unroll
        for (int d = 0; d < 4; ++d) {
            ringA[d] = zA[(size_t)d * NG];
            ringB[d] = zB[(size_t)d * NG];
        }
    }

    // activation constants: lane's own gate is tanh iff q==2
    const float sA = (q == 2) ? 2.0f : 1.0f;
    const float kA = sA * L2E;
    const int lbase = (tid & 31) & ~3;
    const bool lowq = (q < 2);
    const bool oddq = (q & 1);

    float cA = 0.0f, cB = 0.0f, hAlast = 0.0f, hBlast = 0.0f;
    {
        float* p = &sh[0][0][0];
        for (int i = tid; i < 320; i += 256) p[i] = 0.0f;
    }
    __syncthreads();

#pragma unroll 4
    for (int t = 0; t < SEQ; ++t) {
        const int par  = t & 1;
        const int slot = t & 3;

        // ---- partial dots, both batches interleaved ----
        const ulonglong2* vA = (const ulonglong2*)&sh[par][0][20 * q];
        const ulonglong2* vB = (const ulonglong2*)&sh[par][1][20 * q];
        ull aA0 = 0ULL, aA1 = 0ULL, aA2 = 0ULL, aA3 = 0ULL;
        ull aB0 = 0ULL, aB1 = 0ULL, aB2 = 0ULL, aB3 = 0ULL;
#pragma unroll
        for (int p = 0; p < 4; ++p) {
            ulonglong2 dA = vA[p];
            ulonglong2 dB = vB[p];
            ffma2(aA0, w[0 * 8 + 2 * p], dA.x); ffma2(aA0, w[0 * 8 + 2 * p + 1], dA.y);
            ffma2(aB0, w[0 * 8 + 2 * p], dB.x); ffma2(aB0, w[0 * 8 + 2 * p + 1], dB.y);
            ffma2(aA1, w[1 * 8 + 2 * p], dA.x); ffma2(aA1, w[1 * 8 + 2 * p + 1], dA.y);
            ffma2(aB1, w[1 * 8 + 2 * p], dB.x); ffma2(aB1, w[1 * 8 + 2 * p + 1], dB.y);
            ffma2(aA2, w[2 * 8 + 2 * p], dA.x); ffma2(aA2, w[2 * 8 + 2 * p + 1], dA.y);
            ffma2(aB2, w[2 * 8 + 2 * p], dB.x); ffma2(aB2, w[2 * 8 + 2 * p + 1], dB.y);
            ffma2(aA3, w[3 * 8 + 2 * p], dA.x); ffma2(aA3, w[3 * 8 + 2 * p + 1], dA.y);
            ffma2(aB3, w[3 * 8 + 2 * p], dB.x); ffma2(aB3, w[3 * 8 + 2 * p + 1], dB.y);
        }
        float piA, pfA, pgA, poA, piB, pfB, pgB, poB, lo, hi;
        upk2(aA0, lo, hi); piA = lo + hi;
        upk2(aA1, lo, hi); pfA = lo + hi;
        upk2(aA2, lo, hi); pgA = lo + hi;
        upk2(aA3, lo, hi); poA = lo + hi;
        upk2(aB0, lo, hi); piB = lo + hi;
        upk2(aB1, lo, hi); pfB = lo + hi;
        upk2(aB2, lo, hi); pgB = lo + hi;
        upk2(aB3, lo, hi); poB = lo + hi;

        // ---- quad reduce-scatter (both batches) ----
        float kXA = lowq ? piA : pgA, kYA = lowq ? pfA : poA;
        float sXA = lowq ? pgA : piA, sYA = lowq ? poA : pfA;
        float kXB = lowq ? piB : pgB, kYB = lowq ? pfB : poB;
        float sXB = lowq ? pgB : piB, sYB = lowq ? poB : pfB;
        kXA += __shfl_xor_sync(0xffffffffu, sXA, 2, 32);
        kYA += __shfl_xor_sync(0xffffffffu, sYA, 2, 32);
        kXB += __shfl_xor_sync(0xffffffffu, sXB, 2, 32);
        kYB += __shfl_xor_sync(0xffffffffu, sYB, 2, 32);
        float sndA = oddq ? kXA : kYA;
        float sndB = oddq ? kXB : kYB;
        float totA = (oddq ? kYA : kXA) + __shfl_xor_sync(0xffffffffu, sndA, 1, 32);
        float totB = (oddq ? kYB : kXB) + __shfl_xor_sync(0xffffffffu, sndB, 1, 32);

        // ---- add input contribution, prefetch 4 ahead ----
        float gA, gB;
        const int tp = (t + 4 < SEQ) ? (t + 4) : (SEQ - 1);
        if (DIN1) {
            gA = totA + fmaf(wx, ringA[slot], bias);
            gB = totB + fmaf(wx, ringB[slot], bias);
            ringA[slot] = xA[tp];
            ringB[slot] = xB[tp];
        } else {
            gA = totA + ringA[slot];
            gB = totB + ringB[slot];
            ringA[slot] = zA[(size_t)tp * NG];
            ringB[slot] = zB[(size_t)tp * NG];
        }

        // ---- own-gate activation ----
        const float aAv = fmaf(-sA, rcpf(ex2f(gA * kA) + 1.0f), 1.0f);
        const float aBv = fmaf(-sA, rcpf(ex2f(gB * kA) + 1.0f), 1.0f);

        // ---- quad gather + pointwise update ----
        const float aiA = __shfl_sync(0xffffffffu, aAv, lbase + 0, 32);
        const float afA = __shfl_sync(0xffffffffu, aAv, lbase + 1, 32);
        const float agA = __shfl_sync(0xffffffffu, aAv, lbase + 2, 32);
        const float aoA = __shfl_sync(0xffffffffu, aAv, lbase + 3, 32);
        const float aiB = __shfl_sync(0xffffffffu, aBv, lbase + 0, 32);
        const float afB = __shfl_sync(0xffffffffu, aBv, lbase + 1, 32);
        const float agB = __shfl_sync(0xffffffffu, aBv, lbase + 2, 32);
        const float aoB = __shfl_sync(0xffffffffu, aBv, lbase + 3, 32);
        cA = fmaf(afA, cA, aiA * agA);
        cB = fmaf(afB, cB, aiB * agB);
        const float hA = aoA * tanh_f(cA);
        const float hB = aoB * tanh_f(cB);
        hAlast = hA; hBlast = hB;
        if (q == 0) {
            const int hoff = 20 * (u >> 4) + (u & 15);
            sh[par ^ 1][0][hoff] = hA;
            sh[par ^ 1][1][hoff] = hB;
            out_seq[((size_t)b0 * SEQ + t) * HID + u] = hA;
            out_seq[((size_t)(b0 + 1) * SEQ + t) * HID + u] = hB;
        }
        __syncthreads();                            // h(t) visible
    }

    if (q == 0) {
        const size_t yoff = (size_t)NBATCH * SEQ;
        const size_t lh = yoff + (size_t)layer * NBATCH * HID;
        const size_t lc = yoff + (size_t)3 * NBATCH * HID + (size_t)layer * NBATCH * HID;
        d_out[lh + (size_t)b0 * HID + u] = hAlast;
        d_out[lh + (size_t)(b0 + 1) * HID + u] = hBlast;
        d_out[lc + (size_t)b0 * HID + u] = cA;
        d_out[lc + (size_t)(b0 + 1) * HID + u] = cB;
    }
}

// ---------------------------------------------------------------------------
// Final linear: y[r] = dot(g_seqA[r,:], Wlin) + blin.
// ---------------------------------------------------------------------------
__global__ void __launch_bounds__(256)
linear_kernel(const float* __restrict__ Wlin,
              const float* __restrict__ blin,
              float* __restrict__ y) {
    const int lane  = threadIdx.x & 31;
    const int warp  = (blockIdx.x * blockDim.x + threadIdx.x) >> 5;
    const int nwarp = (gridDim.x * blockDim.x) >> 5;
    const float w0 = Wlin[lane];
    const float w1 = Wlin[lane + 32];
    const float bl = blin[0];
    const int nrows = NBATCH * SEQ;
    for (int r = warp; r < nrows; r += nwarp) {
        const float* row = g_seqA + (size_t)r * HID;
        float s = row[lane] * w0 + row[lane + 32] * w1;
#pragma unroll
        for (int o = 16; o; o >>= 1) s += __shfl_down_sync(0xffffffffu, s, o);
        if (lane == 0) y[r] = s + bl;
    }
}

extern "C" void kernel_launch(void* const* d_in, const int* in_sizes, int n_in,
                              void* d_out, int out_size) {
    const float* x    = (const float*)d_in[0];
    const float* Wih0 = (const float*)d_in[1];
    const float* Whh0 = (const float*)d_in[2];
    const float* bih0 = (const float*)d_in[3];
    const float* bhh0 = (const float*)d_in[4];
    const float* Wih1 = (const float*)d_in[5];
    const float* Whh1 = (const float*)d_in[6];
    const float* bih1 = (const float*)d_in[7];
    const float* bhh1 = (const float*)d_in[8];
    const float* Wih2 = (const float*)d_in[9];
    const float* Whh2 = (const float*)d_in[10];
    const float* bih2 = (const float*)d_in[11];
    const float* bhh2 = (const float*)d_in[12];
    const float* Wlin = (const float*)d_in[13];
    const float* blin = (const float*)d_in[14];
    float* out = (float*)d_out;

    float* xzp;  cudaGetSymbolAddress((void**)&xzp, g_xz);
    float* sA;   cudaGetSymbolAddress((void**)&sA, g_seqA);
    float* sB;   cudaGetSymbolAddress((void**)&sB, g_seqB);

    // layer 0: fused (no xz materialization)
    lstm_rec_kernel<true><<<NBATCH / 2, 256>>>(x, nullptr, Wih0, bih0, bhh0,
                                               Whh0, sA, out, 0);

    xz_din64_kernel<<<dim3(SEQ / 32, NBATCH), 256>>>(sA, Wih1, bih1, bhh1, xzp);
    lstm_rec_kernel<false><<<NBATCH / 2, 256>>>(nullptr, xzp, nullptr, nullptr,
                                                nullptr, Whh1, sB, out, 1);

    xz_din64_kernel<<<dim3(SEQ / 32, NBATCH), 256>>>(sB, Wih2, bih2, bhh2, xzp);
    lstm_rec_kernel<false><<<NBATCH / 2, 256>>>(nullptr, xzp, nullptr, nullptr,
                                                nullptr, Whh2, sA, out, 2);

    linear_kernel<<<1024, 256>>>(Wlin, blin, out);
}

// round 9
// speedup vs baseline: 1.7183x; 1.7183x over previous
#include <cuda_runtime.h>

#define HID 64
#define NBATCH 256
#define SEQ 4096
#define NG 256   // 4*HID gates

// Scratch (no cudaMalloc allowed).  g_xz has a 4*NG tail pad so the ring
// prefetch can run 4 steps past the end without bounds checks.
__device__ float g_seqA[(size_t)NBATCH * SEQ * HID];          // 256 MB
__device__ float g_seqB[(size_t)NBATCH * SEQ * HID];          // 256 MB
__device__ float g_xz[(size_t)NBATCH * SEQ * NG + 4 * NG];    // 1 GB + pad

typedef unsigned long long ull;

static __device__ __forceinline__ ull pk2(float lo, float hi) {
    ull r;
    asm("mov.b64 %0, {%1,%2};" : "=l"(r) : "f"(lo), "f"(hi));
    return r;
}
static __device__ __forceinline__ void upk2(ull v, float& lo, float& hi) {
    asm("mov.b64 {%0,%1}, %2;" : "=f"(lo), "=f"(hi) : "l"(v));
}
static __device__ __forceinline__ void ffma2(ull& d, ull a, ull b) {
    asm("fma.rn.f32x2 %0, %1, %2, %0;" : "+l"(d) : "l"(a), "l"(b));
}
static __device__ __forceinline__ float ex2f(float x) {
    float r; asm("ex2.approx.f32 %0, %1;" : "=f"(r) : "f"(x)); return r;
}
static __device__ __forceinline__ float rcpf(float x) {
    float r; asm("rcp.approx.f32 %0, %1;" : "=f"(r) : "f"(x)); return r;
}
#define L2E 1.44269504088896f
// tanh(x) = 1 - 2/(2^(2*L2E*x)+1); overflow-safe both directions.
static __device__ __forceinline__ float tanh_f(float x) {
    return fmaf(-2.0f, rcpf(ex2f(x * (2.0f * L2E)) + 1.0f), 1.0f);
}

// gate remap: storage index tid <-> gate row jg = (tid&3)*HID + (tid>>2)

// ---------------------------------------------------------------------------
// xz precompute, DIN = 64 (gate-remapped output), layers 1-2 only.
// ---------------------------------------------------------------------------
__global__ void __launch_bounds__(256)
xz_din64_kernel(const float* __restrict__ in_seq,   // [B,SEQ,64]
                const float* __restrict__ Wih,      // [256,64]
                const float* __restrict__ bih,
                const float* __restrict__ bhh,
                float* __restrict__ xz) {
    __shared__ __align__(16) float sin_[32][HID];   // 8 KB
    const int tid = threadIdx.x;
    const int jg  = (tid & 3) * HID + (tid >> 2);
    const int b   = blockIdx.y;
    const int t0  = blockIdx.x * 32;

    const float* src = in_seq + ((size_t)b * SEQ + t0) * HID;
#pragma unroll
    for (int k = 0; k < 8; ++k)
        ((float*)sin_)[tid + k * 256] = src[tid + k * 256];

    ull wi[32];
#pragma unroll
    for (int p = 0; p < 32; ++p)
        wi[p] = pk2(Wih[jg * HID + 2 * p], Wih[jg * HID + 2 * p + 1]);
    const float bias = bih[jg] + bhh[jg];
    __syncthreads();

    float* o = xz + ((size_t)b * SEQ + t0) * NG + tid;
#pragma unroll 4
    for (int tt = 0; tt < 32; ++tt) {
        const ulonglong2* v = (const ulonglong2*)&sin_[tt][0];
        ull a0 = pk2(bias, 0.0f), a1 = 0ULL;
#pragma unroll
        for (int p = 0; p < 16; ++p) {
            ulonglong2 q = v[p];
            ffma2(a0, wi[2 * p], q.x);
            ffma2(a1, wi[2 * p + 1], q.y);
        }
        float l0, l1, h0, h1;
        upk2(a0, l0, h0); upk2(a1, l1, h1);
        o[(size_t)tt * NG] = (l0 + h0) + (l1 + h1);
    }
}

// ---------------------------------------------------------------------------
// Recurrent kernel (R7 structure).  1 batch/CTA, 256 CTAs x 256 threads,
// 2 CTAs/SM.  Thread (u = tid>>2, q = tid&3): partial dots of all 4 gates of
// unit u over h-chunk q (4 LDS.128), quad reduce-scatter (2 shuffles) leaves
// lane q holding gate-q preactivation; unified activation (1 ex2 + 1 rcp);
// quad gather (4 shuffles); 1 barrier/step.  h double-buffered, padded smem.
// DIN1=true (layer 0): input contribution computed inline from x scalar.
// DIN1=false: xz streamed via 4-deep ring with bare pointer-bump prefetch
// (g_xz is tail-padded, so no bounds check needed).
// ---------------------------------------------------------------------------
template <bool DIN1>
__global__ void __launch_bounds__(256, 2)
lstm_rec_kernel(const float* __restrict__ x,        // DIN1: [B,SEQ]
                const float* __restrict__ xz,       // !DIN1: [B,SEQ,256] remapped
                const float* __restrict__ Wih,      // DIN1: [256,1]
                const float* __restrict__ bih,
                const float* __restrict__ bhh,
                const float* __restrict__ Whh,      // [256,64]
                float* __restrict__ out_seq,        // [B,SEQ,64]
                float* __restrict__ d_out,
                int layer) {
    __shared__ __align__(16) float sh[2][80];       // 4 chunks * stride 20

    const int tid = threadIdx.x;
    const int b   = blockIdx.x;
    const int u   = tid >> 2;
    const int q   = tid & 3;
    const int jg  = q * HID + u;

    // weights: 4 gate rows of unit u, columns [16q, 16q+16)
    ull w[32];
#pragma unroll
    for (int g = 0; g < 4; ++g) {
        const int row = g * HID + u;
#pragma unroll
        for (int m = 0; m < 8; ++m)
            w[g * 8 + m] = pk2(Whh[row * HID + 16 * q + 2 * m],
                               Whh[row * HID + 16 * q + 2 * m + 1]);
    }

    // input-contribution state
    float wx = 0.0f, bias = 0.0f;
    const float* xp = nullptr;       // DIN1 input stream
    const float* zpref = nullptr;    // !DIN1 prefetch pointer (t+4 row)
    float ring[4];
    if (DIN1) {
        wx   = Wih[jg];
        bias = bih[jg] + bhh[jg];
        xp = x + (size_t)b * SEQ;
#pragma unroll
        for (int d = 0; d < 4; ++d) ring[d] = xp[d];
    } else {
        const float* z = xz + (size_t)b * SEQ * NG + tid;
#pragma unroll
        for (int d = 0; d < 4; ++d) ring[d] = z[(size_t)d * NG];
        zpref = z + (size_t)4 * NG;
    }

    // activation constants: lane's own gate is tanh iff q==2
    const float sA = (q == 2) ? 2.0f : 1.0f;
    const float kA = sA * L2E;
    const int lbase = (tid & 31) & ~3;
    const bool lowq = (q < 2);
    const bool oddq = (q & 1);

    float c = 0.0f, hlast = 0.0f;
    if (tid < 160) sh[tid / 80][tid % 80] = 0.0f;
    __syncthreads();

#pragma unroll 4
    for (int t = 0; t < SEQ; ++t) {
        const int par  = t & 1;                     // static under unroll
        const int slot = t & 3;

        // ---- partial dots: 4 gates over h-chunk q ----
        const ulonglong2* v = (const ulonglong2*)&sh[par][20 * q];
        ull ac0 = 0ULL, ac1 = 0ULL, ac2 = 0ULL, ac3 = 0ULL;
#pragma unroll
        for (int p = 0; p < 4; ++p) {
            ulonglong2 d = v[p];
            ffma2(ac0, w[0 * 8 + 2 * p], d.x); ffma2(ac0, w[0 * 8 + 2 * p + 1], d.y);
            ffma2(ac1, w[1 * 8 + 2 * p], d.x); ffma2(ac1, w[1 * 8 + 2 * p + 1], d.y);
            ffma2(ac2, w[2 * 8 + 2 * p], d.x); ffma2(ac2, w[2 * 8 + 2 * p + 1], d.y);
            ffma2(ac3, w[3 * 8 + 2 * p], d.x); ffma2(ac3, w[3 * 8 + 2 * p + 1], d.y);
        }
        float pi, pf, pg, po, lo, hi;
        upk2(ac0, lo, hi); pi = lo + hi;
        upk2(ac1, lo, hi); pf = lo + hi;
        upk2(ac2, lo, hi); pg = lo + hi;
        upk2(ac3, lo, hi); po = lo + hi;

        // ---- quad reduce-scatter: lane q ends with gate-q total ----
        float kX = lowq ? pi : pg, kY = lowq ? pf : po;
        float sX = lowq ? pg : pi, sY = lowq ? po : pf;
        kX += __shfl_xor_sync(0xffffffffu, sX, 2, 32);
        kY += __shfl_xor_sync(0xffffffffu, sY, 2, 32);
        float snd = oddq ? kX : kY;
        float tot = (oddq ? kY : kX) + __shfl_xor_sync(0xffffffffu, snd, 1, 32);

        // ---- input contribution + prefetch ----
        float g;
        if (DIN1) {
            g = tot + fmaf(wx, ring[slot], bias);
            const int tp = (t + 4 < SEQ) ? (t + 4) : (SEQ - 1);  // no OOB on input
            ring[slot] = xp[tp];
        } else {
            g = tot + ring[slot];
            ring[slot] = *zpref;                    // padded: no bounds check
            zpref += NG;
        }

        // ---- own-gate activation (branch-free, 1 ex2 + 1 rcp) ----
        const float a = fmaf(-sA, rcpf(ex2f(g * kA) + 1.0f), 1.0f);

        // ---- gather quad activations, pointwise update ----
        const float ai = __shfl_sync(0xffffffffu, a, lbase + 0, 32);
        const float af = __shfl_sync(0xffffffffu, a, lbase + 1, 32);
        const float ag = __shfl_sync(0xffffffffu, a, lbase + 2, 32);
        const float ao = __shfl_sync(0xffffffffu, a, lbase + 3, 32);
        c = fmaf(af, c, ai * ag);
        const float h = ao * tanh_f(c);
        hlast = h;
        if (q == 0) {
            sh[par ^ 1][20 * (u >> 4) + (u & 15)] = h;
            out_seq[((size_t)b * SEQ + t) * HID + u] = h;
        }
        __syncthreads();                            // h(t) visible
    }

    if (q == 0) {
        const size_t yoff = (size_t)NBATCH * SEQ;
        d_out[yoff + (size_t)layer * NBATCH * HID + (size_t)b * HID + u] = hlast;
        d_out[yoff + (size_t)3 * NBATCH * HID + (size_t)layer * NBATCH * HID
              + (size_t)b * HID + u] = c;
    }
}

// ---------------------------------------------------------------------------
// Final linear: y[r] = dot(g_seqA[r,:], Wlin) + blin.
// ---------------------------------------------------------------------------
__global__ void __launch_bounds__(256)
linear_kernel(const float* __restrict__ Wlin,
              const float* __restrict__ blin,
              float* __restrict__ y) {
    const int lane  = threadIdx.x & 31;
    const int warp  = (blockIdx.x * blockDim.x + threadIdx.x) >> 5;
    const int nwarp = (gridDim.x * blockDim.x) >> 5;
    const float w0 = Wlin[lane];
    const float w1 = Wlin[lane + 32];
    const float bl = blin[0];
    const int nrows = NBATCH * SEQ;
    for (int r = warp; r < nrows; r += nwarp) {
        const float* row = g_seqA + (size_t)r * HID;
        float s = row[lane] * w0 + row[lane + 32] * w1;
#pragma unroll
        for (int o = 16; o; o >>= 1) s += __shfl_down_sync(0xffffffffu, s, o);
        if (lane == 0) y[r] = s + bl;
    }
}

extern "C" void kernel_launch(void* const* d_in, const int* in_sizes, int n_in,
                              void* d_out, int out_size) {
    const float* x    = (const float*)d_in[0];
    const float* Wih0 = (const float*)d_in[1];
    const float* Whh0 = (const float*)d_in[2];
    const float* bih0 = (const float*)d_in[3];
    const float* bhh0 = (const float*)d_in[4];
    const float* Wih1 = (const float*)d_in[5];
    const float* Whh1 = (const float*)d_in[6];
    const float* bih1 = (const float*)d_in[7];
    const float* bhh1 = (const float*)d_in[8];
    const float* Wih2 = (const float*)d_in[9];
    const float* Whh2 = (const float*)d_in[10];
    const float* bih2 = (const float*)d_in[11];
    const float* bhh2 = (const float*)d_in[12];
    const float* Wlin = (const float*)d_in[13];
    const float* blin = (const float*)d_in[14];
    float* out = (float*)d_out;

    float* xzp;  cudaGetSymbolAddress((void**)&xzp, g_xz);
    float* sA;   cudaGetSymbolAddress((void**)&sA, g_seqA);
    float* sB;   cudaGetSymbolAddress((void**)&sB, g_seqB);

    // layer 0: fused input path (no xz materialization)
    lstm_rec_kernel<true><<<NBATCH, 256>>>(x, nullptr, Wih0, bih0, bhh0,
                                           Whh0, sA, out, 0);

    xz_din64_kernel<<<dim3(SEQ / 32, NBATCH), 256>>>(sA, Wih1, bih1, bhh1, xzp);
    lstm_rec_kernel<false><<<NBATCH, 256>>>(nullptr, xzp, nullptr, nullptr,
                                            nullptr, Whh1, sB, out, 1);

    xz_din64_kernel<<<dim3(SEQ / 32, NBATCH), 256>>>(sB, Wih2, bih2, bhh2, xzp);
    lstm_rec_kernel<false><<<NBATCH, 256>>>(nullptr, xzp, nullptr, nullptr,
                                            nullptr, Whh2, sA, out, 2);

    linear_kernel<<<1024, 256>>>(Wlin, blin, out);
}